// round 5
// baseline (speedup 1.0000x reference)
#include <cuda_runtime.h>
#include <cuda_bf16.h>
#include <math.h>
#include <stdint.h>

#define NV 32768
#define NE 524288
#define NH 128
#define NB 128
#define NPG 256
#define KF 640            // compressed feature cols: state(128) + mean/std/max/min(512)

typedef unsigned short u16;

// ---------------- helpers ----------------
__device__ __forceinline__ uint32_t smem_u32(const void* p) {
    uint32_t a;
    asm("{ .reg .u64 t; cvta.to.shared.u64 t, %1; cvt.u32.u64 %0, t; }" : "=r"(a) : "l"(p));
    return a;
}

#define LDM_X4(r0, r1, r2, r3, addr)                                         \
    asm volatile("ldmatrix.sync.aligned.m8n8.x4.shared.b16 {%0,%1,%2,%3}, [%4];" \
        : "=r"(r0), "=r"(r1), "=r"(r2), "=r"(r3) : "r"(addr))

#define MMA16816(d, a, b0, b1)                                               \
    asm volatile("mma.sync.aligned.m16n8k16.row.col.f32.bf16.bf16.f32 "      \
        "{%0,%1,%2,%3}, {%4,%5,%6,%7}, {%8,%9}, {%0,%1,%2,%3};"              \
        : "+f"((d)[0]), "+f"((d)[1]), "+f"((d)[2]), "+f"((d)[3])             \
        : "r"((a)[0]), "r"((a)[1]), "r"((a)[2]), "r"((a)[3]),                \
          "r"(b0), "r"(b1))

#define CP16(dst, src)                                                       \
    asm volatile("{ .reg .u64 g; cvta.to.global.u64 g, %1; "                 \
        "cp.async.ca.shared.global [%0], [g], 16; }"                         \
        :: "r"(dst), "l"(src) : "memory")
#define CP_COMMIT() asm volatile("cp.async.commit_group;" ::: "memory")
#define CP_WAIT1()  asm volatile("cp.async.wait_group 1;" ::: "memory")
#define CP_WAIT0()  asm volatile("cp.async.wait_group 0;" ::: "memory")

__device__ __forceinline__ void cvt2(float a, float b, uint32_t& hi, uint32_t& lo) {
    __nv_bfloat16 ha = __float2bfloat16_rn(a), hb = __float2bfloat16_rn(b);
    float ra = a - __bfloat162float(ha);
    float rb = b - __bfloat162float(hb);
    __nv_bfloat16 la = __float2bfloat16_rn(ra), lb = __float2bfloat16_rn(rb);
    u16 uha = *(u16*)&ha, uhb = *(u16*)&hb;
    u16 ula = *(u16*)&la, ulb = *(u16*)&lb;
    hi = ((uint32_t)uhb << 16) | uha;
    lo = ((uint32_t)ulb << 16) | ula;
}

__device__ __forceinline__ void wsplit(u16* ph, u16* pl, float v) {
    __nv_bfloat16 h = __float2bfloat16_rn(v);
    float r = v - __bfloat162float(h);
    __nv_bfloat16 l = __float2bfloat16_rn(r);
    *ph = *(u16*)&h; *pl = *(u16*)&l;
}

// ---------------- scratch ----------------
__device__ int   g_cnt[NV];
__device__ int   g_off[NV + 1];
__device__ int   g_cur[NV];
__device__ int   g_csr[NE];
__device__ float g_logd[NV];
__device__ float g_amp[NV];
__device__ float g_att[NV];
__device__ float g_avg;
__device__ float g_lossb[NB];
__device__ float g_zero128[NH];
__device__ float g_Ap[NV * NH];
__device__ float g_Bp[NV * NH];
__device__ float g_h1[NV * NH];
__device__ float g_A1[NV * 2];
__device__ float g_B1[NV * 2];
__device__ float g_feat1[NV * 26];
// split bf16 planes
__device__ __align__(16) u16 g_sh[NV * NH];          // state hi
__device__ __align__(16) u16 g_sl[NV * NH];          // state lo
__device__ __align__(16) u16 g_ph[NV * NH];          // post-combined hi
__device__ __align__(16) u16 g_pl[NV * NH];          // post-combined lo
__device__ __align__(16) u16 g_fh[(size_t)NV * KF];  // feat hi [V,640]
__device__ __align__(16) u16 g_fl[(size_t)NV * KF];  // feat lo
// weight planes (K-major [128, K])
__device__ __align__(16) u16 g_W0h[NH * KF],  g_W0l[NH * KF];    // [Wx;W0] K=640
__device__ __align__(16) u16 g_W1h[NH * 512], g_W1l[NH * 512];
__device__ __align__(16) u16 g_W2h[NH * 512], g_W2l[NH * 512];
__device__ __align__(16) u16 g_WpAh[NH * NH], g_WpAl[NH * NH];   // pre top
__device__ __align__(16) u16 g_WpBh[NH * NH], g_WpBl[NH * NH];   // pre bottom
__device__ __align__(16) u16 g_Wlh[NH * NH],  g_Wll[NH * NH];    // lin
__device__ __align__(16) u16 g_Wl1h[NH * NH], g_Wl1l[NH * NH];   // lin1
__device__ __align__(16) u16 g_Wr1h[NH * NH], g_Wr1l[NH * NH];   // r1

// ---------------- setup kernels ----------------
__global__ void k_zero() {
    int i = blockIdx.x * blockDim.x + threadIdx.x;
    if (i < NV) { g_cnt[i] = 0; g_cur[i] = 0; }
    if (i < NB) g_lossb[i] = 0.f;
    if (i < NH) g_zero128[i] = 0.f;
    if (i == 0) g_avg = 0.f;
}

__global__ void k_hist(const int* __restrict__ ei) {
    int e = blockIdx.x * blockDim.x + threadIdx.x;
    if (e < NE) atomicAdd(&g_cnt[ei[NE + e]], 1);
}

__global__ void k_scan() {
    __shared__ int sums[1024];
    int t = threadIdx.x;
    int base = t * 32;
    int loc[32];
    int s = 0;
#pragma unroll
    for (int i = 0; i < 32; i++) { loc[i] = s; s += g_cnt[base + i]; }
    sums[t] = s;
    __syncthreads();
    for (int d = 1; d < 1024; d <<= 1) {
        int v = (t >= d) ? sums[t - d] : 0;
        __syncthreads();
        sums[t] += v;
        __syncthreads();
    }
    int excl = sums[t] - s;
#pragma unroll
    for (int i = 0; i < 32; i++) g_off[base + i] = excl + loc[i];
    if (t == 1023) g_off[NV] = excl + s;
}

__global__ void k_scatter(const int* __restrict__ ei) {
    int e = blockIdx.x * blockDim.x + threadIdx.x;
    if (e < NE) {
        int d = ei[NE + e];
        int p = g_off[d] + atomicAdd(&g_cur[d], 1);
        g_csr[p] = ei[e];
    }
}

__global__ void k_degstat() {
    int v = blockIdx.x * blockDim.x + threadIdx.x;
    int d = g_cnt[v];
    float degc = fmaxf((float)d, 1.f);
    g_logd[v] = logf(degc + 1.f);
    float l = logf((float)d + 1.f);
#pragma unroll
    for (int s = 16; s; s >>= 1) l += __shfl_xor_sync(0xffffffffu, l, s);
    if ((threadIdx.x & 31) == 0) atomicAdd(&g_avg, l);
}

__global__ void k_ampatt() {
    int v = blockIdx.x * blockDim.x + threadIdx.x;
    float avg = g_avg / (float)NV;
    float logd = g_logd[v];
    g_amp[v] = logd / avg;
    g_att[v] = avg / logd;
}

// ---------------- weight transpose+split ----------------
__global__ void k_tsplit(const float* __restrict__ W, u16* __restrict__ Wh,
                         u16* __restrict__ Wl, int K) {
    __shared__ float tile[32][33];
    int kb = blockIdx.x * 32, nb = blockIdx.y * 32;
    int tx = threadIdx.x, ty = threadIdx.y;
    for (int i = ty; i < 32; i += 8)
        tile[i][tx] = W[(kb + i) * NH + nb + tx];
    __syncthreads();
    for (int i = ty; i < 32; i += 8)
        wsplit(&Wh[(nb + i) * K + kb + tx], &Wl[(nb + i) * K + kb + tx], tile[tx][i]);
}

// ---------------- layer 1 (feature dim 2) ----------------
__global__ void k_pre1(const float* __restrict__ x, const float* __restrict__ w,
                       const float* __restrict__ b) {
    int v = blockIdx.x * blockDim.x + threadIdx.x;
    float x0 = x[2 * v], x1 = x[2 * v + 1];
    g_A1[2 * v + 0] = x0 * w[0] + x1 * w[2] + b[0];
    g_A1[2 * v + 1] = x0 * w[1] + x1 * w[3] + b[1];
    g_B1[2 * v + 0] = x0 * w[4] + x1 * w[6];
    g_B1[2 * v + 1] = x0 * w[5] + x1 * w[7];
}

__global__ void k_agg1(const float* __restrict__ x) {
    int v = blockIdx.x * blockDim.x + threadIdx.x;
    if (v >= NV) return;
    int beg = g_off[v], end = g_off[v + 1];
    float a0 = g_A1[2 * v], a1 = g_A1[2 * v + 1];
    float s0 = 0, s1 = 0, q0 = 0, q1 = 0;
    float mx0 = -3.4e38f, mx1 = -3.4e38f, mn0 = 3.4e38f, mn1 = 3.4e38f;
    for (int e = beg; e < end; e++) {
        int s = g_csr[e];
        float h0 = a0 + g_B1[2 * s];
        float h1 = a1 + g_B1[2 * s + 1];
        s0 += h0; s1 += h1; q0 += h0 * h0; q1 += h1 * h1;
        mx0 = fmaxf(mx0, h0); mx1 = fmaxf(mx1, h1);
        mn0 = fminf(mn0, h0); mn1 = fminf(mn1, h1);
    }
    int d = end - beg;
    float degc = d > 0 ? (float)d : 1.f;
    float m0 = s0 / degc, m1 = s1 / degc;
    float sd0 = sqrtf(fmaxf(q0 / degc - m0 * m0, 0.f) + 1e-5f);
    float sd1 = sqrtf(fmaxf(q1 / degc - m1 * m1, 0.f) + 1e-5f);
    if (d == 0) { mx0 = mx1 = mn0 = mn1 = 0.f; }
    float am = g_amp[v], at = g_att[v];
    float* fr = g_feat1 + v * 26;
    fr[0] = x[2 * v]; fr[1] = x[2 * v + 1];
    fr[2] = m0;  fr[3] = m1;  fr[4] = sd0;  fr[5] = sd1;
    fr[6] = mx0; fr[7] = mx1; fr[8] = mn0;  fr[9] = mn1;
    fr[10] = m0 * am;  fr[11] = m1 * am;  fr[12] = sd0 * am; fr[13] = sd1 * am;
    fr[14] = mx0 * am; fr[15] = mx1 * am; fr[16] = mn0 * am; fr[17] = mn1 * am;
    fr[18] = m0 * at;  fr[19] = m1 * at;  fr[20] = sd0 * at; fr[21] = sd1 * at;
    fr[22] = mx0 * at; fr[23] = mx1 * at; fr[24] = mn0 * at; fr[25] = mn1 * at;
}

__global__ void k_post1(const float* __restrict__ w, const float* __restrict__ b) {
    __shared__ float fr[26];
    int v = blockIdx.x;
    int c = threadIdx.x;
    if (c < 26) fr[c] = g_feat1[v * 26 + c];
    __syncthreads();
    float acc = b[c];
#pragma unroll
    for (int k = 0; k < 26; k++) acc += fr[k] * w[k * NH + c];
    wsplit(&g_ph[v * NH + c], &g_pl[v * NH + c], acc);
}

// ---------------- fused multi-accumulator GEMM ----------------
// M-tile 64, N=128, up to 3 weight sets share the staged A tile.
// Warp w: row block (w&3)*16, col half (w>>2)*64 (4 groups of 16 cols).
// MODE 0: NACC fp32 outputs (out0 w/bias0, out1 w/bias1)        [pre pair]
// MODE 1: combine acc0 + amp*acc1 + att*acc2 (+bias0) -> planes [post triple]
// MODE 2: acc0 + bias0 -> split planes                          [lin]
// MODE 3: acc0 + bias0, leaky -> fp32                           [r1]
template<int NACC, int MODE>
__global__ void __launch_bounds__(256) k_gm(
    const u16* __restrict__ Ah, const u16* __restrict__ Al, int lda, int K0,
    int kst, int K12,
    const u16* __restrict__ B0h, const u16* __restrict__ B0l,
    const u16* __restrict__ B1h, const u16* __restrict__ B1l,
    const u16* __restrict__ B2h, const u16* __restrict__ B2l,
    const float* __restrict__ bias0, const float* __restrict__ bias1,
    const float* __restrict__ amp, const float* __restrict__ att,
    float* __restrict__ outf0, float* __restrict__ outf1,
    u16* __restrict__ outh, u16* __restrict__ outl) {
    constexpr int CHUNK = 10240 + NACC * 20480;
    extern __shared__ char dsm[];
    uint32_t sb = smem_u32(dsm);
    int t = threadIdx.x, w = t >> 5, lane = t & 31;
    int m0 = blockIdx.x * 64;
    int rblk = (w & 3) * 16, cbh = (w >> 2) * 64;

    float acc[NACC][4][2][4];
#pragma unroll
    for (int s = 0; s < NACC; s++)
#pragma unroll
        for (int g = 0; g < 4; g++)
#pragma unroll
            for (int h = 0; h < 2; h++)
#pragma unroll
                for (int i = 0; i < 4; i++) acc[s][g][h][i] = 0.f;

    // load mappings
    int arow = t >> 2, aseg = (t & 3) * 8;
    const u16* aHp = Ah + (size_t)(m0 + arow) * lda + aseg;
    const u16* aLp = Al + (size_t)(m0 + arow) * lda + aseg;
    uint32_t aso = (uint32_t)(arow * 40 + aseg) * 2;
    int brow = t >> 1, bcol = (t & 1) * 16;
    uint32_t bso = (uint32_t)(brow * 40 + bcol) * 2;
    const u16* BH[3] = {B0h, B1h, B2h};
    const u16* BL[3] = {B0l, B1l, B2l};

    int nch = K0 >> 5;

    auto issue = [&](int ch) {
        int k0 = ch << 5;
        uint32_t bb = sb + (uint32_t)(ch & 1) * CHUNK;
        CP16(bb + aso, aHp + k0);
        CP16(bb + 5120 + aso, aLp + k0);
#pragma unroll
        for (int s = 0; s < NACC; s++) {
            int kb = (s == 0) ? k0 : k0 - kst;
            int Ks = (s == 0) ? K0 : K12;
            if (kb >= 0) {
                const u16* sh = BH[s] + (size_t)brow * Ks + kb + bcol;
                const u16* sl = BL[s] + (size_t)brow * Ks + kb + bcol;
                uint32_t d = bb + 10240 + (uint32_t)s * 20480 + bso;
                CP16(d, sh); CP16(d + 16, sh + 8);
                CP16(d + 10240, sl); CP16(d + 10240 + 16, sl + 8);
            }
        }
        CP_COMMIT();
    };

    int frow = lane & 15, fcol = (lane >> 4) * 8;
    uint32_t abase = (uint32_t)((rblk + frow) * 40 + fcol) * 2;

    issue(0);
    for (int ch = 0; ch < nch; ch++) {
        if (ch + 1 < nch) { issue(ch + 1); CP_WAIT1(); }
        else { CP_WAIT0(); }
        __syncthreads();
        int k0 = ch << 5;
        uint32_t bb = sb + (uint32_t)(ch & 1) * CHUNK;
#pragma unroll
        for (int kk = 0; kk < 2; kk++) {
            uint32_t ko = kk * 32;
            uint32_t ah[4], al[4];
            LDM_X4(ah[0], ah[1], ah[2], ah[3], bb + abase + ko);
            LDM_X4(al[0], al[1], al[2], al[3], bb + 5120 + abase + ko);
#pragma unroll
            for (int s = 0; s < NACC; s++) {
                if (s > 0 && k0 < kst) continue;
                uint32_t Bb = bb + 10240 + (uint32_t)s * 20480;
#pragma unroll
                for (int g = 0; g < 4; g++) {
                    uint32_t bbase = (uint32_t)((cbh + g * 16 + frow) * 40 + fcol) * 2;
                    uint32_t bh0, bh1, bh2, bh3, bl0, bl1, bl2, bl3;
                    LDM_X4(bh0, bh1, bh2, bh3, Bb + bbase + ko);
                    LDM_X4(bl0, bl1, bl2, bl3, Bb + 10240 + bbase + ko);
                    MMA16816(acc[s][g][0], ah, bh0, bh2);
                    MMA16816(acc[s][g][0], ah, bl0, bl2);
                    MMA16816(acc[s][g][0], al, bh0, bh2);
                    MMA16816(acc[s][g][1], ah, bh1, bh3);
                    MMA16816(acc[s][g][1], ah, bl1, bl3);
                    MMA16816(acc[s][g][1], al, bh1, bh3);
                }
            }
        }
        __syncthreads();
    }

    // ---------------- epilogue ----------------
    float* stage = (float*)dsm;
    int r0 = rblk + (lane >> 2);
    int cb2 = (lane & 3) * 2;

    if (MODE == 0) {
        for (int s = 0; s < NACC; s++) {
            __syncthreads();
#pragma unroll
            for (int g = 0; g < 4; g++)
#pragma unroll
                for (int h = 0; h < 2; h++) {
                    int col = cbh + g * 16 + h * 8 + cb2;
                    stage[r0 * 132 + col] = acc[s][g][h][0];
                    stage[r0 * 132 + col + 1] = acc[s][g][h][1];
                    stage[(r0 + 8) * 132 + col] = acc[s][g][h][2];
                    stage[(r0 + 8) * 132 + col + 1] = acc[s][g][h][3];
                }
            __syncthreads();
            float* o = (s == 0) ? outf0 : outf1;
            const float* bi = (s == 0) ? bias0 : bias1;
#pragma unroll
            for (int i = 0; i < 8; i++) {
                int idx = t + i * 256;
                int row = idx >> 5;
                int c4 = (idx & 31) * 4;
                float4 v = *(const float4*)(stage + row * 132 + c4);
                v.x += __ldg(&bi[c4]); v.y += __ldg(&bi[c4 + 1]);
                v.z += __ldg(&bi[c4 + 2]); v.w += __ldg(&bi[c4 + 3]);
                *(float4*)(o + (size_t)(m0 + row) * 128 + c4) = v;
            }
        }
    } else if (MODE == 1) {
        float am0 = amp[m0 + r0], at0 = att[m0 + r0];
        float am8 = amp[m0 + r0 + 8], at8 = att[m0 + r0 + 8];
        __syncthreads();
#pragma unroll
        for (int g = 0; g < 4; g++)
#pragma unroll
            for (int h = 0; h < 2; h++) {
                int col = cbh + g * 16 + h * 8 + cb2;
                stage[r0 * 132 + col] =
                    acc[0][g][h][0] + am0 * acc[1][g][h][0] + at0 * acc[2][g][h][0];
                stage[r0 * 132 + col + 1] =
                    acc[0][g][h][1] + am0 * acc[1][g][h][1] + at0 * acc[2][g][h][1];
                stage[(r0 + 8) * 132 + col] =
                    acc[0][g][h][2] + am8 * acc[1][g][h][2] + at8 * acc[2][g][h][2];
                stage[(r0 + 8) * 132 + col + 1] =
                    acc[0][g][h][3] + am8 * acc[1][g][h][3] + at8 * acc[2][g][h][3];
            }
        __syncthreads();
#pragma unroll
        for (int i = 0; i < 8; i++) {
            int idx = t + i * 256;
            int row = idx >> 5;
            int c4 = (idx & 31) * 4;
            float4 v = *(const float4*)(stage + row * 132 + c4);
            v.x += __ldg(&bias0[c4]); v.y += __ldg(&bias0[c4 + 1]);
            v.z += __ldg(&bias0[c4 + 2]); v.w += __ldg(&bias0[c4 + 3]);
            uint32_t h0, l0, h1, l1;
            cvt2(v.x, v.y, h0, l0); cvt2(v.z, v.w, h1, l1);
            uint2 hv = {h0, h1}, lv = {l0, l1};
            size_t go = (size_t)(m0 + row) * 128 + c4;
            *(uint2*)(outh + go) = hv;
            *(uint2*)(outl + go) = lv;
        }
    } else {
        __syncthreads();
#pragma unroll
        for (int g = 0; g < 4; g++)
#pragma unroll
            for (int h = 0; h < 2; h++) {
                int col = cbh + g * 16 + h * 8 + cb2;
                stage[r0 * 132 + col] = acc[0][g][h][0];
                stage[r0 * 132 + col + 1] = acc[0][g][h][1];
                stage[(r0 + 8) * 132 + col] = acc[0][g][h][2];
                stage[(r0 + 8) * 132 + col + 1] = acc[0][g][h][3];
            }
        __syncthreads();
#pragma unroll
        for (int i = 0; i < 8; i++) {
            int idx = t + i * 256;
            int row = idx >> 5;
            int c4 = (idx & 31) * 4;
            float4 v = *(const float4*)(stage + row * 132 + c4);
            v.x += __ldg(&bias0[c4]); v.y += __ldg(&bias0[c4 + 1]);
            v.z += __ldg(&bias0[c4 + 2]); v.w += __ldg(&bias0[c4 + 3]);
            size_t go = (size_t)(m0 + row) * 128 + c4;
            if (MODE == 3) {
                if (v.x < 0.f) v.x *= 0.01f;
                if (v.y < 0.f) v.y *= 0.01f;
                if (v.z < 0.f) v.z *= 0.01f;
                if (v.w < 0.f) v.w *= 0.01f;
                *(float4*)(outf0 + go) = v;
            } else {
                uint32_t h0, l0, h1, l1;
                cvt2(v.x, v.y, h0, l0); cvt2(v.z, v.w, h1, l1);
                uint2 hv = {h0, h1}, lv = {l0, l1};
                *(uint2*)(outh + go) = hv;
                *(uint2*)(outl + go) = lv;
            }
        }
    }
}

// ---------------- aggregation: writes split-bf16 feat [V,640] ----------------
__global__ void __launch_bounds__(128) k_agg() {
    __shared__ int s_src[128];
    int v = blockIdx.x;
    int f = threadIdx.x;
    int beg = g_off[v], end = g_off[v + 1];
    float a = g_Ap[v * NH + f];
    float sum = 0.f, sq = 0.f, mx = -3.4e38f, mn = 3.4e38f;
    for (int base = beg; base < end; base += 128) {
        int n = min(128, end - base);
        if (f < n) s_src[f] = g_csr[base + f];
        __syncthreads();
        int e = 0;
        for (; e + 4 <= n; e += 4) {
            int i0 = s_src[e], i1 = s_src[e + 1], i2 = s_src[e + 2], i3 = s_src[e + 3];
            float h0 = a + g_Bp[i0 * NH + f];
            float h1 = a + g_Bp[i1 * NH + f];
            float h2 = a + g_Bp[i2 * NH + f];
            float h3 = a + g_Bp[i3 * NH + f];
            sum += h0 + h1 + h2 + h3;
            sq += h0 * h0 + h1 * h1 + h2 * h2 + h3 * h3;
            mx = fmaxf(mx, fmaxf(fmaxf(h0, h1), fmaxf(h2, h3)));
            mn = fminf(mn, fminf(fminf(h0, h1), fminf(h2, h3)));
        }
        for (; e < n; e++) {
            float h = a + g_Bp[s_src[e] * NH + f];
            sum += h; sq += h * h; mx = fmaxf(mx, h); mn = fminf(mn, h);
        }
        __syncthreads();
    }
    int d = end - beg;
    float degc = d > 0 ? (float)d : 1.f;
    float mean = sum / degc;
    float stdv = sqrtf(fmaxf(sq / degc - mean * mean, 0.f) + 1e-5f);
    if (d == 0) { mx = 0.f; mn = 0.f; }
    size_t fb = (size_t)v * KF;
    g_fh[fb + f] = g_sh[v * NH + f];
    g_fl[fb + f] = g_sl[v * NH + f];
    wsplit(&g_fh[fb + 128 + f], &g_fl[fb + 128 + f], mean);
    wsplit(&g_fh[fb + 256 + f], &g_fl[fb + 256 + f], stdv);
    wsplit(&g_fh[fb + 384 + f], &g_fl[fb + 384 + f], mx);
    wsplit(&g_fh[fb + 512 + f], &g_fl[fb + 512 + f], mn);
}

// ---------------- readout tail ----------------
__global__ void __launch_bounds__(256) k_readout(const float* __restrict__ r2w,
                                                 const float* __restrict__ r2b,
                                                 const float* __restrict__ r3w,
                                                 const float* __restrict__ r3b,
                                                 const float* __restrict__ tgt,
                                                 float* __restrict__ out) {
    __shared__ float w2[128 * 8];
    int t = threadIdx.x;
    for (int i = t; i < 128 * 8; i += 256) w2[i] = r2w[i];
    __syncthreads();
    int warp = t >> 5, lane = t & 31;
    int v = blockIdx.x * 8 + warp;
    const float* h1 = g_h1 + v * NH;
    float p[8] = {0, 0, 0, 0, 0, 0, 0, 0};
    for (int k = lane; k < 128; k += 32) {
        float hv = h1[k];
#pragma unroll
        for (int j = 0; j < 8; j++) p[j] += hv * w2[k * 8 + j];
    }
#pragma unroll
    for (int j = 0; j < 8; j++)
#pragma unroll
        for (int s = 16; s; s >>= 1) p[j] += __shfl_xor_sync(0xffffffffu, p[j], s);
    if (lane == 0) {
        float h2[8];
#pragma unroll
        for (int j = 0; j < 8; j++) {
            float x = p[j] + r2b[j];
            h2[j] = x < 0.f ? 0.01f * x : x;
        }
        float err = 0.f;
#pragma unroll
        for (int c = 0; c < 3; c++) {
            float o = r3b[c];
#pragma unroll
            for (int j = 0; j < 8; j++) o += h2[j] * r3w[j * 3 + c];
            if (o < 0.f) o *= 0.01f;
            out[v * 3 + c] = o;
            float dd = o - tgt[v * 3 + c];
            err += dd * dd;
        }
        atomicAdd(&g_lossb[v >> 8], err);
    }
}

__global__ void k_loss(float* __restrict__ out) {
    __shared__ float s[128];
    int b = threadIdx.x;
    float l = g_lossb[b] / (float)(NPG * 3);
    out[NV * 3 + 1 + b] = l;
    s[b] = l;
    __syncthreads();
    for (int d = 64; d; d >>= 1) {
        if (b < d) s[b] += s[b + d];
        __syncthreads();
    }
    if (b == 0) out[NV * 3] = s[0] / (float)NB;
}

// ---------------- host ----------------
template <typename T>
static void* symv(T& s) { void* p = nullptr; cudaGetSymbolAddress(&p, s); return p; }

extern "C" void kernel_launch(void* const* d_in, const int* in_sizes, int n_in,
                              void* d_out, int out_size) {
    const float* x       = (const float*)d_in[0];
    const int*   ei      = (const int*)d_in[1];
    const float* tgt_n   = (const float*)d_in[2];
    const float* pre1_w  = (const float*)d_in[4];
    const float* pre1_b  = (const float*)d_in[5];
    const float* post1_w = (const float*)d_in[6];
    const float* post1_b = (const float*)d_in[7];
    const float* lin1_w  = (const float*)d_in[8];
    const float* lin1_b  = (const float*)d_in[9];
    const float* pre_w   = (const float*)d_in[10];
    const float* pre_b   = (const float*)d_in[11];
    const float* post_w  = (const float*)d_in[12];
    const float* post_b  = (const float*)d_in[13];
    const float* lin_w   = (const float*)d_in[14];
    const float* lin_b   = (const float*)d_in[15];
    const float* r1_w    = (const float*)d_in[16];
    const float* r1_b    = (const float*)d_in[17];
    const float* r2_w    = (const float*)d_in[18];
    const float* r2_b    = (const float*)d_in[19];
    const float* r3_w    = (const float*)d_in[20];
    const float* r3_b    = (const float*)d_in[21];
    float* out = (float*)d_out;

    float* p_Ap  = (float*)symv(g_Ap);
    float* p_Bp  = (float*)symv(g_Bp);
    float* p_h1  = (float*)symv(g_h1);
    float* p_amp = (float*)symv(g_amp);
    float* p_att = (float*)symv(g_att);
    float* p_z   = (float*)symv(g_zero128);
    u16* p_sh  = (u16*)symv(g_sh);   u16* p_sl  = (u16*)symv(g_sl);
    u16* p_ph  = (u16*)symv(g_ph);   u16* p_pl  = (u16*)symv(g_pl);
    u16* p_fh  = (u16*)symv(g_fh);   u16* p_fl  = (u16*)symv(g_fl);
    u16* p_W0h = (u16*)symv(g_W0h);  u16* p_W0l = (u16*)symv(g_W0l);
    u16* p_W1h = (u16*)symv(g_W1h);  u16* p_W1l = (u16*)symv(g_W1l);
    u16* p_W2h = (u16*)symv(g_W2h);  u16* p_W2l = (u16*)symv(g_W2l);
    u16* p_WpAh = (u16*)symv(g_WpAh); u16* p_WpAl = (u16*)symv(g_WpAl);
    u16* p_WpBh = (u16*)symv(g_WpBh); u16* p_WpBl = (u16*)symv(g_WpBl);
    u16* p_Wlh = (u16*)symv(g_Wlh);   u16* p_Wll = (u16*)symv(g_Wll);
    u16* p_Wl1h = (u16*)symv(g_Wl1h); u16* p_Wl1l = (u16*)symv(g_Wl1l);
    u16* p_Wr1h = (u16*)symv(g_Wr1h); u16* p_Wr1l = (u16*)symv(g_Wr1l);

    const int SM1 = 2 * (10240 + 1 * 20480);   // 61440
    const int SM2 = 2 * (10240 + 2 * 20480);   // 102400
    const int SM3 = 2 * (10240 + 3 * 20480);   // 143360
    cudaFuncSetAttribute(k_gm<1, 2>, cudaFuncAttributeMaxDynamicSharedMemorySize, SM1);
    cudaFuncSetAttribute(k_gm<1, 3>, cudaFuncAttributeMaxDynamicSharedMemorySize, SM1);
    cudaFuncSetAttribute(k_gm<2, 0>, cudaFuncAttributeMaxDynamicSharedMemorySize, SM2);
    cudaFuncSetAttribute(k_gm<3, 1>, cudaFuncAttributeMaxDynamicSharedMemorySize, SM3);

    // graph setup
    k_zero<<<NV / 256, 256>>>();
    k_hist<<<NE / 256, 256>>>(ei);
    k_scan<<<1, 1024>>>();
    k_scatter<<<NE / 256, 256>>>(ei);
    k_degstat<<<NV / 256, 256>>>();
    k_ampatt<<<NV / 256, 256>>>();

    // weight transposes + splits (once per launch)
    dim3 tb(32, 8);
    k_tsplit<<<dim3(4, 4), tb>>>(lin1_w, p_Wl1h, p_Wl1l, NH);
    k_tsplit<<<dim3(4, 4), tb>>>(pre_w, p_WpAh, p_WpAl, NH);
    k_tsplit<<<dim3(4, 4), tb>>>(pre_w + NH * NH, p_WpBh, p_WpBl, NH);
    k_tsplit<<<dim3(KF / 32, 4), tb>>>(post_w, p_W0h, p_W0l, KF);
    k_tsplit<<<dim3(16, 4), tb>>>(post_w + 640 * NH, p_W1h, p_W1l, 512);
    k_tsplit<<<dim3(16, 4), tb>>>(post_w + 1152 * NH, p_W2h, p_W2l, 512);
    k_tsplit<<<dim3(4, 4), tb>>>(lin_w, p_Wlh, p_Wll, NH);
    k_tsplit<<<dim3(4, 4), tb>>>(r1_w, p_Wr1h, p_Wr1l, NH);

    // layer 1 (2 -> 128): post1 -> planes; lin1 -> state planes
    k_pre1<<<NV / 256, 256>>>(x, pre1_w, pre1_b);
    k_agg1<<<NV / 256, 256>>>(x);
    k_post1<<<NV, 128>>>(post1_w, post1_b);
    k_gm<1, 2><<<NV / 64, 256, SM1>>>(p_ph, p_pl, NH, NH, 0, NH,
        p_Wl1h, p_Wl1l, 0, 0, 0, 0, lin1_b, p_z, 0, 0, 0, 0, p_sh, p_sl);

    // 3 propagation layers
    for (int p = 0; p < 3; p++) {
        // fused pre: Ap (bias) + Bp
        k_gm<2, 0><<<NV / 64, 256, SM2>>>(p_sh, p_sl, NH, NH, 0, NH,
            p_WpAh, p_WpAl, p_WpBh, p_WpBl, 0, 0, pre_b, p_z, 0, 0,
            p_Ap, p_Bp, 0, 0);
        k_agg<<<NV, 128>>>();
        // fused post triple + combine -> planes
        k_gm<3, 1><<<NV / 64, 256, SM3>>>(p_fh, p_fl, KF, KF, 128, 512,
            p_W0h, p_W0l, p_W1h, p_W1l, p_W2h, p_W2l, post_b, p_z,
            p_amp, p_att, 0, 0, p_ph, p_pl);
        // lin -> state planes
        k_gm<1, 2><<<NV / 64, 256, SM1>>>(p_ph, p_pl, NH, NH, 0, NH,
            p_Wlh, p_Wll, 0, 0, 0, 0, lin_b, p_z, 0, 0, 0, 0, p_sh, p_sl);
    }

    // readout
    k_gm<1, 3><<<NV / 64, 256, SM1>>>(p_sh, p_sl, NH, NH, 0, NH,
        p_Wr1h, p_Wr1l, 0, 0, 0, 0, r1_b, p_z, 0, 0, p_h1, 0, 0, 0);
    k_readout<<<NV / 8, 256>>>(r2_w, r2_b, r3_w, r3_b, tgt_n, out);
    k_loss<<<1, 128>>>(out);

    (void)in_sizes; (void)n_in; (void)out_size;
}

// round 6
// speedup vs baseline: 1.0034x; 1.0034x over previous
#include <cuda_runtime.h>
#include <cuda_bf16.h>
#include <math.h>
#include <stdint.h>

#define NV 32768
#define NE 524288
#define NH 128
#define NB 128
#define NPG 256
#define KF 640

typedef unsigned short u16;

// ---------------- helpers ----------------
__device__ __forceinline__ uint32_t smem_u32(const void* p) {
    uint32_t a;
    asm("{ .reg .u64 t; cvta.to.shared.u64 t, %1; cvt.u32.u64 %0, t; }" : "=r"(a) : "l"(p));
    return a;
}

#define LDM_X4(r0, r1, r2, r3, addr)                                         \
    asm volatile("ldmatrix.sync.aligned.m8n8.x4.shared.b16 {%0,%1,%2,%3}, [%4];" \
        : "=r"(r0), "=r"(r1), "=r"(r2), "=r"(r3) : "r"(addr))

#define MMA16816(d, a, b0, b1)                                               \
    asm volatile("mma.sync.aligned.m16n8k16.row.col.f32.bf16.bf16.f32 "      \
        "{%0,%1,%2,%3}, {%4,%5,%6,%7}, {%8,%9}, {%0,%1,%2,%3};"              \
        : "+f"((d)[0]), "+f"((d)[1]), "+f"((d)[2]), "+f"((d)[3])             \
        : "r"((a)[0]), "r"((a)[1]), "r"((a)[2]), "r"((a)[3]),                \
          "r"(b0), "r"(b1))

#define CP16(dst, src)                                                       \
    asm volatile("{ .reg .u64 g; cvta.to.global.u64 g, %1; "                 \
        "cp.async.ca.shared.global [%0], [g], 16; }"                         \
        :: "r"(dst), "l"(src) : "memory")
#define CP_COMMIT() asm volatile("cp.async.commit_group;" ::: "memory")
#define CP_WAIT1()  asm volatile("cp.async.wait_group 1;" ::: "memory")
#define CP_WAIT0()  asm volatile("cp.async.wait_group 0;" ::: "memory")

__device__ __forceinline__ void cvt2(float a, float b, uint32_t& hi, uint32_t& lo) {
    __nv_bfloat16 ha = __float2bfloat16_rn(a), hb = __float2bfloat16_rn(b);
    float ra = a - __bfloat162float(ha);
    float rb = b - __bfloat162float(hb);
    __nv_bfloat16 la = __float2bfloat16_rn(ra), lb = __float2bfloat16_rn(rb);
    u16 uha = *(u16*)&ha, uhb = *(u16*)&hb;
    u16 ula = *(u16*)&la, ulb = *(u16*)&lb;
    hi = ((uint32_t)uhb << 16) | uha;
    lo = ((uint32_t)ulb << 16) | ula;
}

__device__ __forceinline__ void wsplit(u16* ph, u16* pl, float v) {
    __nv_bfloat16 h = __float2bfloat16_rn(v);
    float r = v - __bfloat162float(h);
    __nv_bfloat16 l = __float2bfloat16_rn(r);
    *ph = *(u16*)&h; *pl = *(u16*)&l;
}

// ---------------- scratch ----------------
__device__ int   g_cnt[NV];
__device__ int   g_off[NV + 1];
__device__ int   g_cur[NV];
__device__ int   g_csr[NE];
__device__ float g_logd[NV];
__device__ float g_amp[NV];
__device__ float g_att[NV];
__device__ float g_avg;
__device__ float g_lossb[NB];
__device__ float g_Ap[NV * NH];
__device__ float g_Bp[NV * NH];
__device__ float g_h1[NV * NH];
__device__ float g_A1[NV * 2];
__device__ float g_B1[NV * 2];
__device__ float g_feat1[NV * 26];
// split bf16 planes
__device__ __align__(16) u16 g_sh[NV * NH];
__device__ __align__(16) u16 g_sl[NV * NH];
__device__ __align__(16) u16 g_ph[NV * NH];
__device__ __align__(16) u16 g_pl[NV * NH];
__device__ __align__(16) u16 g_fh[(size_t)NV * KF];
__device__ __align__(16) u16 g_fl[(size_t)NV * KF];
// weight planes (K-major)
__device__ __align__(16) u16 g_W0h[NH * KF],  g_W0l[NH * KF];
__device__ __align__(16) u16 g_W1h[NH * 512], g_W1l[NH * 512];
__device__ __align__(16) u16 g_W2h[NH * 512], g_W2l[NH * 512];
__device__ __align__(16) u16 g_WpAh[NH * NH], g_WpAl[NH * NH];
__device__ __align__(16) u16 g_WpBh[NH * NH], g_WpBl[NH * NH];
__device__ __align__(16) u16 g_Wlh[NH * NH],  g_Wll[NH * NH];
__device__ __align__(16) u16 g_Wl1h[NH * NH], g_Wl1l[NH * NH];
__device__ __align__(16) u16 g_Wr1h[NH * NH], g_Wr1l[NH * NH];

// ---------------- setup kernels ----------------
__global__ void k_zero() {
    int i = blockIdx.x * blockDim.x + threadIdx.x;
    if (i < NV) { g_cnt[i] = 0; g_cur[i] = 0; }
    if (i < NB) g_lossb[i] = 0.f;
    if (i == 0) g_avg = 0.f;
}

__global__ void k_hist(const int* __restrict__ ei) {
    int e = blockIdx.x * blockDim.x + threadIdx.x;
    if (e < NE) atomicAdd(&g_cnt[ei[NE + e]], 1);
}

__global__ void k_scan() {
    __shared__ int sums[1024];
    int t = threadIdx.x;
    int base = t * 32;
    int loc[32];
    int s = 0;
#pragma unroll
    for (int i = 0; i < 32; i++) { loc[i] = s; s += g_cnt[base + i]; }
    sums[t] = s;
    __syncthreads();
    for (int d = 1; d < 1024; d <<= 1) {
        int v = (t >= d) ? sums[t - d] : 0;
        __syncthreads();
        sums[t] += v;
        __syncthreads();
    }
    int excl = sums[t] - s;
#pragma unroll
    for (int i = 0; i < 32; i++) g_off[base + i] = excl + loc[i];
    if (t == 1023) g_off[NV] = excl + s;
}

__global__ void k_scatter(const int* __restrict__ ei) {
    int e = blockIdx.x * blockDim.x + threadIdx.x;
    if (e < NE) {
        int d = ei[NE + e];
        int p = g_off[d] + atomicAdd(&g_cur[d], 1);
        g_csr[p] = ei[e];
    }
}

__global__ void k_degstat() {
    int v = blockIdx.x * blockDim.x + threadIdx.x;
    int d = g_cnt[v];
    float degc = fmaxf((float)d, 1.f);
    g_logd[v] = logf(degc + 1.f);
    float l = logf((float)d + 1.f);
#pragma unroll
    for (int s = 16; s; s >>= 1) l += __shfl_xor_sync(0xffffffffu, l, s);
    if ((threadIdx.x & 31) == 0) atomicAdd(&g_avg, l);
}

__global__ void k_ampatt() {
    int v = blockIdx.x * blockDim.x + threadIdx.x;
    float avg = g_avg / (float)NV;
    float logd = g_logd[v];
    g_amp[v] = logd / avg;
    g_att[v] = avg / logd;
}

// ---------------- weight transpose+split ----------------
__global__ void k_tsplit(const float* __restrict__ W, u16* __restrict__ Wh,
                         u16* __restrict__ Wl, int K) {
    __shared__ float tile[32][33];
    int kb = blockIdx.x * 32, nb = blockIdx.y * 32;
    int tx = threadIdx.x, ty = threadIdx.y;
    for (int i = ty; i < 32; i += 8)
        tile[i][tx] = W[(kb + i) * NH + nb + tx];
    __syncthreads();
    for (int i = ty; i < 32; i += 8)
        wsplit(&Wh[(nb + i) * K + kb + tx], &Wl[(nb + i) * K + kb + tx], tile[tx][i]);
}

// ---------------- layer 1 (feature dim 2) ----------------
__global__ void k_pre1(const float* __restrict__ x, const float* __restrict__ w,
                       const float* __restrict__ b) {
    int v = blockIdx.x * blockDim.x + threadIdx.x;
    float x0 = x[2 * v], x1 = x[2 * v + 1];
    g_A1[2 * v + 0] = x0 * w[0] + x1 * w[2] + b[0];
    g_A1[2 * v + 1] = x0 * w[1] + x1 * w[3] + b[1];
    g_B1[2 * v + 0] = x0 * w[4] + x1 * w[6];
    g_B1[2 * v + 1] = x0 * w[5] + x1 * w[7];
}

__global__ void k_agg1(const float* __restrict__ x) {
    int v = blockIdx.x * blockDim.x + threadIdx.x;
    if (v >= NV) return;
    int beg = g_off[v], end = g_off[v + 1];
    float a0 = g_A1[2 * v], a1 = g_A1[2 * v + 1];
    float s0 = 0, s1 = 0, q0 = 0, q1 = 0;
    float mx0 = -3.4e38f, mx1 = -3.4e38f, mn0 = 3.4e38f, mn1 = 3.4e38f;
    for (int e = beg; e < end; e++) {
        int s = g_csr[e];
        float h0 = a0 + g_B1[2 * s];
        float h1 = a1 + g_B1[2 * s + 1];
        s0 += h0; s1 += h1; q0 += h0 * h0; q1 += h1 * h1;
        mx0 = fmaxf(mx0, h0); mx1 = fmaxf(mx1, h1);
        mn0 = fminf(mn0, h0); mn1 = fminf(mn1, h1);
    }
    int d = end - beg;
    float degc = d > 0 ? (float)d : 1.f;
    float m0 = s0 / degc, m1 = s1 / degc;
    float sd0 = sqrtf(fmaxf(q0 / degc - m0 * m0, 0.f) + 1e-5f);
    float sd1 = sqrtf(fmaxf(q1 / degc - m1 * m1, 0.f) + 1e-5f);
    if (d == 0) { mx0 = mx1 = mn0 = mn1 = 0.f; }
    float am = g_amp[v], at = g_att[v];
    float* fr = g_feat1 + v * 26;
    fr[0] = x[2 * v]; fr[1] = x[2 * v + 1];
    fr[2] = m0;  fr[3] = m1;  fr[4] = sd0;  fr[5] = sd1;
    fr[6] = mx0; fr[7] = mx1; fr[8] = mn0;  fr[9] = mn1;
    fr[10] = m0 * am;  fr[11] = m1 * am;  fr[12] = sd0 * am; fr[13] = sd1 * am;
    fr[14] = mx0 * am; fr[15] = mx1 * am; fr[16] = mn0 * am; fr[17] = mn1 * am;
    fr[18] = m0 * at;  fr[19] = m1 * at;  fr[20] = sd0 * at; fr[21] = sd1 * at;
    fr[22] = mx0 * at; fr[23] = mx1 * at; fr[24] = mn0 * at; fr[25] = mn1 * at;
}

__global__ void k_post1(const float* __restrict__ w, const float* __restrict__ b) {
    __shared__ float fr[26];
    int v = blockIdx.x;
    int c = threadIdx.x;
    if (c < 26) fr[c] = g_feat1[v * 26 + c];
    __syncthreads();
    float acc = b[c];
#pragma unroll
    for (int k = 0; k < 26; k++) acc += fr[k] * w[k * NH + c];
    wsplit(&g_ph[v * NH + c], &g_pl[v * NH + c], acc);
}

// ---------------- fused prop kernel ----------------
// M-tile 64, 256 threads, warp w: rows (w&3)*16.., cols (w>>2)*64..
// main loop: NMAIN accumulator sets over A planes (pipelined cp.async).
// NMAIN==3: combine amp/att + post_b -> D1; chain lin (Wl) -> D2.
// NMAIN==1: D2 = main + bias0 directly.
// D2 -> global state planes + smem; chain2: R1? r1 (leaky->out0) : pre pair (out0/out1).
template<int NMAIN, int R1>
__global__ void __launch_bounds__(256) k_fused(
    const u16* __restrict__ Ah, const u16* __restrict__ Al, int lda, int K0,
    int kst, int K12,
    const u16* __restrict__ B0h, const u16* __restrict__ B0l,
    const u16* __restrict__ B1h, const u16* __restrict__ B1l,
    const u16* __restrict__ B2h, const u16* __restrict__ B2l,
    const float* __restrict__ bias0,
    const float* __restrict__ amp, const float* __restrict__ att,
    const u16* __restrict__ Wlh, const u16* __restrict__ Wll,
    const float* __restrict__ linb,
    const u16* __restrict__ WAh, const u16* __restrict__ WAl,
    const float* __restrict__ bA,
    const u16* __restrict__ WBh, const u16* __restrict__ WBl,
    float* __restrict__ out0, float* __restrict__ out1,
    u16* __restrict__ sth, u16* __restrict__ stl) {
    constexpr int CHUNK = 10240 + NMAIN * 20480;
    extern __shared__ char dsm[];
    uint32_t sb = smem_u32(dsm);
    int t = threadIdx.x, w = t >> 5, lane = t & 31;
    int m0 = blockIdx.x * 64;
    int rblk = (w & 3) * 16, cbh = (w >> 2) * 64;

    float acc[NMAIN][4][2][4];
#pragma unroll
    for (int s = 0; s < NMAIN; s++)
#pragma unroll
        for (int g = 0; g < 4; g++)
#pragma unroll
            for (int h = 0; h < 2; h++)
#pragma unroll
                for (int i = 0; i < 4; i++) acc[s][g][h][i] = 0.f;

    int arow = t >> 2, aseg = (t & 3) * 8;
    const u16* aHp = Ah + (size_t)(m0 + arow) * lda + aseg;
    const u16* aLp = Al + (size_t)(m0 + arow) * lda + aseg;
    uint32_t aso = (uint32_t)(arow * 40 + aseg) * 2;
    int brow = t >> 1, bcol = (t & 1) * 16;
    uint32_t bso = (uint32_t)(brow * 40 + bcol) * 2;
    const u16* BH[3] = {B0h, B1h, B2h};
    const u16* BL[3] = {B0l, B1l, B2l};

    int nch = K0 >> 5;
    auto issue = [&](int ch) {
        int k0 = ch << 5;
        uint32_t bb = sb + (uint32_t)(ch & 1) * CHUNK;
        CP16(bb + aso, aHp + k0);
        CP16(bb + 5120 + aso, aLp + k0);
#pragma unroll
        for (int s = 0; s < NMAIN; s++) {
            int kb = (s == 0) ? k0 : k0 - kst;
            int Ks = (s == 0) ? K0 : K12;
            if (kb >= 0) {
                const u16* sh = BH[s] + (size_t)brow * Ks + kb + bcol;
                const u16* sl = BL[s] + (size_t)brow * Ks + kb + bcol;
                uint32_t d = bb + 10240 + (uint32_t)s * 20480 + bso;
                CP16(d, sh); CP16(d + 16, sh + 8);
                CP16(d + 10240, sl); CP16(d + 10240 + 16, sl + 8);
            }
        }
        CP_COMMIT();
    };

    int frow = lane & 15, fcol = (lane >> 4) * 8;
    uint32_t abase = (uint32_t)((rblk + frow) * 40 + fcol) * 2;

    issue(0);
    for (int ch = 0; ch < nch; ch++) {
        if (ch + 1 < nch) { issue(ch + 1); CP_WAIT1(); }
        else { CP_WAIT0(); }
        __syncthreads();
        int k0 = ch << 5;
        uint32_t bb = sb + (uint32_t)(ch & 1) * CHUNK;
#pragma unroll
        for (int kk = 0; kk < 2; kk++) {
            uint32_t ko = kk * 32;
            uint32_t ah[4], al[4];
            LDM_X4(ah[0], ah[1], ah[2], ah[3], bb + abase + ko);
            LDM_X4(al[0], al[1], al[2], al[3], bb + 5120 + abase + ko);
#pragma unroll
            for (int s = 0; s < NMAIN; s++) {
                if (s > 0 && k0 < kst) continue;
                uint32_t Bb = bb + 10240 + (uint32_t)s * 20480;
#pragma unroll
                for (int g = 0; g < 4; g++) {
                    uint32_t bbase = (uint32_t)((cbh + g * 16 + frow) * 40 + fcol) * 2;
                    uint32_t bh0, bh1, bh2, bh3, bl0, bl1, bl2, bl3;
                    LDM_X4(bh0, bh1, bh2, bh3, Bb + bbase + ko);
                    LDM_X4(bl0, bl1, bl2, bl3, Bb + 10240 + bbase + ko);
                    MMA16816(acc[s][g][0], ah, bh0, bh2);
                    MMA16816(acc[s][g][0], ah, bl0, bl2);
                    MMA16816(acc[s][g][0], al, bh0, bh2);
                    MMA16816(acc[s][g][1], ah, bh1, bh3);
                    MMA16816(acc[s][g][1], ah, bl1, bl3);
                    MMA16816(acc[s][g][1], al, bh1, bh3);
                }
            }
        }
        __syncthreads();
    }

    // ---- D frags ----
    int r0 = rblk + (lane >> 2);
    int cb2 = (lane & 3) * 2;
    uint32_t cA = sb, cB = sb + 40960;
    float d[4][2][4];

    // helper lambdas
    auto frag_store = [&](float dd[4][2][4]) {
#pragma unroll
        for (int g = 0; g < 4; g++)
#pragma unroll
            for (int h = 0; h < 2; h++) {
                int col0 = cbh + g * 16 + h * 8 + cb2;
                int ck = col0 >> 5, cc = col0 & 31;
                uint32_t h01, l01, h23, l23;
                cvt2(dd[g][h][0], dd[g][h][1], h01, l01);
                cvt2(dd[g][h][2], dd[g][h][3], h23, l23);
                uint32_t base = cA + (uint32_t)ck * 5120 + (uint32_t)cc * 2;
                uint32_t a0 = base + (uint32_t)(r0 * 40) * 2;
                uint32_t a8 = base + (uint32_t)((r0 + 8) * 40) * 2;
                asm volatile("st.shared.b32 [%0], %1;" :: "r"(a0), "r"(h01) : "memory");
                asm volatile("st.shared.b32 [%0], %1;" :: "r"(a8), "r"(h23) : "memory");
                asm volatile("st.shared.b32 [%0], %1;" :: "r"(a0 + 20480), "r"(l01) : "memory");
                asm volatile("st.shared.b32 [%0], %1;" :: "r"(a8 + 20480), "r"(l23) : "memory");
            }
    };

    auto chain = [&](const u16* W0H, const u16* W0L, const u16* W1H, const u16* W1L,
                     int ns, float out[2][4][2][4]) {
        for (int c = 0; c < 4; c++) {
            // stage B chunk (ns sets)
            for (int s = 0; s < ns; s++) {
                const u16* wh = (s == 0) ? W0H : W1H;
                const u16* wl = (s == 0) ? W0L : W1L;
                const u16* srcH = wh + brow * 128 + c * 32 + bcol;
                const u16* srcL = wl + brow * 128 + c * 32 + bcol;
                uint32_t dst = cB + (uint32_t)s * 20480 + bso;
                CP16(dst, srcH); CP16(dst + 16, srcH + 8);
                CP16(dst + 10240, srcL); CP16(dst + 10240 + 16, srcL + 8);
            }
            CP_COMMIT();
            CP_WAIT0();
            __syncthreads();
#pragma unroll
            for (int kk = 0; kk < 2; kk++) {
                uint32_t ko = kk * 32;
                uint32_t ah[4], al[4];
                uint32_t aBase = cA + (uint32_t)c * 5120 + abase;
                LDM_X4(ah[0], ah[1], ah[2], ah[3], aBase + ko);
                LDM_X4(al[0], al[1], al[2], al[3], aBase + 20480 + ko);
                for (int s = 0; s < ns; s++) {
                    uint32_t Bb = cB + (uint32_t)s * 20480;
#pragma unroll
                    for (int g = 0; g < 4; g++) {
                        uint32_t bbase = (uint32_t)((cbh + g * 16 + frow) * 40 + fcol) * 2;
                        uint32_t bh0, bh1, bh2, bh3, bl0, bl1, bl2, bl3;
                        LDM_X4(bh0, bh1, bh2, bh3, Bb + bbase + ko);
                        LDM_X4(bl0, bl1, bl2, bl3, Bb + 10240 + bbase + ko);
                        MMA16816(out[s][g][0], ah, bh0, bh2);
                        MMA16816(out[s][g][0], ah, bl0, bl2);
                        MMA16816(out[s][g][0], al, bh0, bh2);
                        MMA16816(out[s][g][1], ah, bh1, bh3);
                        MMA16816(out[s][g][1], ah, bl1, bl3);
                        MMA16816(out[s][g][1], al, bh1, bh3);
                    }
                }
            }
            __syncthreads();
        }
    };

    if (NMAIN == 3) {
        float am0 = amp[m0 + r0], at0 = att[m0 + r0];
        float am8 = amp[m0 + r0 + 8], at8 = att[m0 + r0 + 8];
#pragma unroll
        for (int g = 0; g < 4; g++)
#pragma unroll
            for (int h = 0; h < 2; h++) {
                int col0 = cbh + g * 16 + h * 8 + cb2;
                float b0 = __ldg(&bias0[col0]), b1 = __ldg(&bias0[col0 + 1]);
                d[g][h][0] = acc[0][g][h][0] + am0 * acc[1][g][h][0] + at0 * acc[2][g][h][0] + b0;
                d[g][h][1] = acc[0][g][h][1] + am0 * acc[1][g][h][1] + at0 * acc[2][g][h][1] + b1;
                d[g][h][2] = acc[0][g][h][2] + am8 * acc[1][g][h][2] + at8 * acc[2][g][h][2] + b0;
                d[g][h][3] = acc[0][g][h][3] + am8 * acc[1][g][h][3] + at8 * acc[2][g][h][3] + b1;
            }
        // lin chain: D1 -> smem, x Wl -> D2
        frag_store(d);
        __syncthreads();
        float a2[2][4][2][4];
#pragma unroll
        for (int g = 0; g < 4; g++)
#pragma unroll
            for (int h = 0; h < 2; h++)
#pragma unroll
                for (int i = 0; i < 4; i++) a2[0][g][h][i] = 0.f;
        chain(Wlh, Wll, 0, 0, 1, a2);
#pragma unroll
        for (int g = 0; g < 4; g++)
#pragma unroll
            for (int h = 0; h < 2; h++) {
                int col0 = cbh + g * 16 + h * 8 + cb2;
                float b0 = __ldg(&linb[col0]), b1 = __ldg(&linb[col0 + 1]);
                d[g][h][0] = a2[0][g][h][0] + b0;
                d[g][h][1] = a2[0][g][h][1] + b1;
                d[g][h][2] = a2[0][g][h][2] + b0;
                d[g][h][3] = a2[0][g][h][3] + b1;
            }
    } else {
#pragma unroll
        for (int g = 0; g < 4; g++)
#pragma unroll
            for (int h = 0; h < 2; h++) {
                int col0 = cbh + g * 16 + h * 8 + cb2;
                float b0 = __ldg(&bias0[col0]), b1 = __ldg(&bias0[col0 + 1]);
                d[g][h][0] = acc[0][g][h][0] + b0;
                d[g][h][1] = acc[0][g][h][1] + b1;
                d[g][h][2] = acc[0][g][h][2] + b0;
                d[g][h][3] = acc[0][g][h][3] + b1;
            }
    }

    // D2 -> global state planes + smem A
#pragma unroll
    for (int g = 0; g < 4; g++)
#pragma unroll
        for (int h = 0; h < 2; h++) {
            int col0 = cbh + g * 16 + h * 8 + cb2;
            uint32_t h01, l01, h23, l23;
            cvt2(d[g][h][0], d[g][h][1], h01, l01);
            cvt2(d[g][h][2], d[g][h][3], h23, l23);
            size_t o0 = (size_t)(m0 + r0) * 128 + col0;
            size_t o8 = (size_t)(m0 + r0 + 8) * 128 + col0;
            *(uint32_t*)(sth + o0) = h01; *(uint32_t*)(stl + o0) = l01;
            *(uint32_t*)(sth + o8) = h23; *(uint32_t*)(stl + o8) = l23;
        }
    frag_store(d);
    __syncthreads();

    constexpr int NS2 = R1 ? 1 : 2;
    float a3[2][4][2][4];
#pragma unroll
    for (int s = 0; s < NS2; s++)
#pragma unroll
        for (int g = 0; g < 4; g++)
#pragma unroll
            for (int h = 0; h < 2; h++)
#pragma unroll
                for (int i = 0; i < 4; i++) a3[s][g][h][i] = 0.f;
    chain(WAh, WAl, WBh, WBl, NS2, a3);

#pragma unroll
    for (int g = 0; g < 4; g++)
#pragma unroll
        for (int h = 0; h < 2; h++) {
            int col0 = cbh + g * 16 + h * 8 + cb2;
            float b0 = __ldg(&bA[col0]), b1 = __ldg(&bA[col0 + 1]);
            size_t o0 = (size_t)(m0 + r0) * 128 + col0;
            size_t o8 = (size_t)(m0 + r0 + 8) * 128 + col0;
            if (R1) {
                float v0 = a3[0][g][h][0] + b0, v1 = a3[0][g][h][1] + b1;
                float v2 = a3[0][g][h][2] + b0, v3 = a3[0][g][h][3] + b1;
                if (v0 < 0.f) v0 *= 0.01f;
                if (v1 < 0.f) v1 *= 0.01f;
                if (v2 < 0.f) v2 *= 0.01f;
                if (v3 < 0.f) v3 *= 0.01f;
                float2 p0 = {v0, v1}, p8 = {v2, v3};
                *(float2*)(out0 + o0) = p0;
                *(float2*)(out0 + o8) = p8;
            } else {
                float2 p0 = {a3[0][g][h][0] + b0, a3[0][g][h][1] + b1};
                float2 p8 = {a3[0][g][h][2] + b0, a3[0][g][h][3] + b1};
                *(float2*)(out0 + o0) = p0;
                *(float2*)(out0 + o8) = p8;
                float2 q0 = {a3[1][g][h][0], a3[1][g][h][1]};
                float2 q8 = {a3[1][g][h][2], a3[1][g][h][3]};
                *(float2*)(out1 + o0) = q0;
                *(float2*)(out1 + o8) = q8;
            }
        }
}

// ---------------- aggregation ----------------
__global__ void __launch_bounds__(128) k_agg() {
    __shared__ int s_src[128];
    int v = blockIdx.x;
    int f = threadIdx.x;
    int beg = g_off[v], end = g_off[v + 1];
    float a = g_Ap[v * NH + f];
    float sum = 0.f, sq = 0.f, mx = -3.4e38f, mn = 3.4e38f;
    for (int base = beg; base < end; base += 128) {
        int n = min(128, end - base);
        if (f < n) s_src[f] = g_csr[base + f];
        __syncthreads();
        int e = 0;
        for (; e + 4 <= n; e += 4) {
            int i0 = s_src[e], i1 = s_src[e + 1], i2 = s_src[e + 2], i3 = s_src[e + 3];
            float h0 = a + g_Bp[i0 * NH + f];
            float h1 = a + g_Bp[i1 * NH + f];
            float h2 = a + g_Bp[i2 * NH + f];
            float h3 = a + g_Bp[i3 * NH + f];
            sum += h0 + h1 + h2 + h3;
            sq += h0 * h0 + h1 * h1 + h2 * h2 + h3 * h3;
            mx = fmaxf(mx, fmaxf(fmaxf(h0, h1), fmaxf(h2, h3)));
            mn = fminf(mn, fminf(fminf(h0, h1), fminf(h2, h3)));
        }
        for (; e < n; e++) {
            float h = a + g_Bp[s_src[e] * NH + f];
            sum += h; sq += h * h; mx = fmaxf(mx, h); mn = fminf(mn, h);
        }
        __syncthreads();
    }
    int d = end - beg;
    float degc = d > 0 ? (float)d : 1.f;
    float mean = sum / degc;
    float stdv = sqrtf(fmaxf(sq / degc - mean * mean, 0.f) + 1e-5f);
    if (d == 0) { mx = 0.f; mn = 0.f; }
    size_t fb = (size_t)v * KF;
    g_fh[fb + f] = g_sh[v * NH + f];
    g_fl[fb + f] = g_sl[v * NH + f];
    wsplit(&g_fh[fb + 128 + f], &g_fl[fb + 128 + f], mean);
    wsplit(&g_fh[fb + 256 + f], &g_fl[fb + 256 + f], stdv);
    wsplit(&g_fh[fb + 384 + f], &g_fl[fb + 384 + f], mx);
    wsplit(&g_fh[fb + 512 + f], &g_fl[fb + 512 + f], mn);
}

// ---------------- readout tail ----------------
__global__ void __launch_bounds__(256) k_readout(const float* __restrict__ r2w,
                                                 const float* __restrict__ r2b,
                                                 const float* __restrict__ r3w,
                                                 const float* __restrict__ r3b,
                                                 const float* __restrict__ tgt,
                                                 float* __restrict__ out) {
    __shared__ float w2[128 * 8];
    int t = threadIdx.x;
    for (int i = t; i < 128 * 8; i += 256) w2[i] = r2w[i];
    __syncthreads();
    int warp = t >> 5, lane = t & 31;
    int v = blockIdx.x * 8 + warp;
    const float* h1 = g_h1 + v * NH;
    float p[8] = {0, 0, 0, 0, 0, 0, 0, 0};
    for (int k = lane; k < 128; k += 32) {
        float hv = h1[k];
#pragma unroll
        for (int j = 0; j < 8; j++) p[j] += hv * w2[k * 8 + j];
    }
#pragma unroll
    for (int j = 0; j < 8; j++)
#pragma unroll
        for (int s = 16; s; s >>= 1) p[j] += __shfl_xor_sync(0xffffffffu, p[j], s);
    if (lane == 0) {
        float h2[8];
#pragma unroll
        for (int j = 0; j < 8; j++) {
            float x = p[j] + r2b[j];
            h2[j] = x < 0.f ? 0.01f * x : x;
        }
        float err = 0.f;
#pragma unroll
        for (int c = 0; c < 3; c++) {
            float o = r3b[c];
#pragma unroll
            for (int j = 0; j < 8; j++) o += h2[j] * r3w[j * 3 + c];
            if (o < 0.f) o *= 0.01f;
            out[v * 3 + c] = o;
            float dd = o - tgt[v * 3 + c];
            err += dd * dd;
        }
        atomicAdd(&g_lossb[v >> 8], err);
    }
}

__global__ void k_loss(float* __restrict__ out) {
    __shared__ float s[128];
    int b = threadIdx.x;
    float l = g_lossb[b] / (float)(NPG * 3);
    out[NV * 3 + 1 + b] = l;
    s[b] = l;
    __syncthreads();
    for (int d = 64; d; d >>= 1) {
        if (b < d) s[b] += s[b + d];
        __syncthreads();
    }
    if (b == 0) out[NV * 3] = s[0] / (float)NB;
}

// ---------------- host ----------------
template <typename T>
static void* symv(T& s) { void* p = nullptr; cudaGetSymbolAddress(&p, s); return p; }

extern "C" void kernel_launch(void* const* d_in, const int* in_sizes, int n_in,
                              void* d_out, int out_size) {
    const float* x       = (const float*)d_in[0];
    const int*   ei      = (const int*)d_in[1];
    const float* tgt_n   = (const float*)d_in[2];
    const float* pre1_w  = (const float*)d_in[4];
    const float* pre1_b  = (const float*)d_in[5];
    const float* post1_w = (const float*)d_in[6];
    const float* post1_b = (const float*)d_in[7];
    const float* lin1_w  = (const float*)d_in[8];
    const float* lin1_b  = (const float*)d_in[9];
    const float* pre_w   = (const float*)d_in[10];
    const float* pre_b   = (const float*)d_in[11];
    const float* post_w  = (const float*)d_in[12];
    const float* post_b  = (const float*)d_in[13];
    const float* lin_w   = (const float*)d_in[14];
    const float* lin_b   = (const float*)d_in[15];
    const float* r1_w    = (const float*)d_in[16];
    const float* r1_b    = (const float*)d_in[17];
    const float* r2_w    = (const float*)d_in[18];
    const float* r2_b    = (const float*)d_in[19];
    const float* r3_w    = (const float*)d_in[20];
    const float* r3_b    = (const float*)d_in[21];
    float* out = (float*)d_out;

    float* p_Ap  = (float*)symv(g_Ap);
    float* p_Bp  = (float*)symv(g_Bp);
    float* p_h1  = (float*)symv(g_h1);
    float* p_amp = (float*)symv(g_amp);
    float* p_att = (float*)symv(g_att);
    u16* p_sh  = (u16*)symv(g_sh);   u16* p_sl  = (u16*)symv(g_sl);
    u16* p_ph  = (u16*)symv(g_ph);   u16* p_pl  = (u16*)symv(g_pl);
    u16* p_fh  = (u16*)symv(g_fh);   u16* p_fl  = (u16*)symv(g_fl);
    u16* p_W0h = (u16*)symv(g_W0h);  u16* p_W0l = (u16*)symv(g_W0l);
    u16* p_W1h = (u16*)symv(g_W1h);  u16* p_W1l = (u16*)symv(g_W1l);
    u16* p_W2h = (u16*)symv(g_W2h);  u16* p_W2l = (u16*)symv(g_W2l);
    u16* p_WpAh = (u16*)symv(g_WpAh); u16* p_WpAl = (u16*)symv(g_WpAl);
    u16* p_WpBh = (u16*)symv(g_WpBh); u16* p_WpBl = (u16*)symv(g_WpBl);
    u16* p_Wlh = (u16*)symv(g_Wlh);   u16* p_Wll = (u16*)symv(g_Wll);
    u16* p_Wl1h = (u16*)symv(g_Wl1h); u16* p_Wl1l = (u16*)symv(g_Wl1l);
    u16* p_Wr1h = (u16*)symv(g_Wr1h); u16* p_Wr1l = (u16*)symv(g_Wr1l);

    const int SMF1 = 81920;                 // max(2*30720, 81920)
    const int SMF3 = 2 * (10240 + 3 * 20480);  // 143360
    cudaFuncSetAttribute(k_fused<1, 0>, cudaFuncAttributeMaxDynamicSharedMemorySize, SMF1);
    cudaFuncSetAttribute(k_fused<3, 0>, cudaFuncAttributeMaxDynamicSharedMemorySize, SMF3);
    cudaFuncSetAttribute(k_fused<3, 1>, cudaFuncAttributeMaxDynamicSharedMemorySize, SMF3);

    // graph setup
    k_zero<<<NV / 256, 256>>>();
    k_hist<<<NE / 256, 256>>>(ei);
    k_scan<<<1, 1024>>>();
    k_scatter<<<NE / 256, 256>>>(ei);
    k_degstat<<<NV / 256, 256>>>();
    k_ampatt<<<NV / 256, 256>>>();

    // weight transposes + splits
    dim3 tb(32, 8);
    k_tsplit<<<dim3(4, 4), tb>>>(lin1_w, p_Wl1h, p_Wl1l, NH);
    k_tsplit<<<dim3(4, 4), tb>>>(pre_w, p_WpAh, p_WpAl, NH);
    k_tsplit<<<dim3(4, 4), tb>>>(pre_w + NH * NH, p_WpBh, p_WpBl, NH);
    k_tsplit<<<dim3(KF / 32, 4), tb>>>(post_w, p_W0h, p_W0l, KF);
    k_tsplit<<<dim3(16, 4), tb>>>(post_w + 640 * NH, p_W1h, p_W1l, 512);
    k_tsplit<<<dim3(16, 4), tb>>>(post_w + 1152 * NH, p_W2h, p_W2l, 512);
    k_tsplit<<<dim3(4, 4), tb>>>(lin_w, p_Wlh, p_Wll, NH);
    k_tsplit<<<dim3(4, 4), tb>>>(r1_w, p_Wr1h, p_Wr1l, NH);

    // layer 1: pre1/agg1/post1 -> ph planes; fused lin1 + chained pre pair
    k_pre1<<<NV / 256, 256>>>(x, pre1_w, pre1_b);
    k_agg1<<<NV / 256, 256>>>(x);
    k_post1<<<NV, 128>>>(post1_w, post1_b);
    k_fused<1, 0><<<NV / 64, 256, SMF1>>>(
        p_ph, p_pl, NH, NH, 0, NH,
        p_Wl1h, p_Wl1l, 0, 0, 0, 0,
        lin1_b, 0, 0, 0, 0, 0,
        p_WpAh, p_WpAl, pre_b, p_WpBh, p_WpBl,
        p_Ap, p_Bp, p_sh, p_sl);

    // 3 propagation layers: agg then fused (post3+combine -> lin -> pre/r1)
    for (int p = 0; p < 3; p++) {
        k_agg<<<NV, 128>>>();
        if (p < 2) {
            k_fused<3, 0><<<NV / 64, 256, SMF3>>>(
                p_fh, p_fl, KF, KF, 128, 512,
                p_W0h, p_W0l, p_W1h, p_W1l, p_W2h, p_W2l,
                post_b, p_amp, p_att, p_Wlh, p_Wll, lin_b,
                p_WpAh, p_WpAl, pre_b, p_WpBh, p_WpBl,
                p_Ap, p_Bp, p_sh, p_sl);
        } else {
            k_fused<3, 1><<<NV / 64, 256, SMF3>>>(
                p_fh, p_fl, KF, KF, 128, 512,
                p_W0h, p_W0l, p_W1h, p_W1l, p_W2h, p_W2l,
                post_b, p_amp, p_att, p_Wlh, p_Wll, lin_b,
                p_Wr1h, p_Wr1l, r1_b, 0, 0,
                p_h1, 0, p_sh, p_sl);
        }
    }

    k_readout<<<NV / 8, 256>>>(r2_w, r2_b, r3_w, r3_b, tgt_n, out);
    k_loss<<<1, 128>>>(out);

    (void)in_sizes; (void)n_in; (void)out_size;
}